// round 6
// baseline (speedup 1.0000x reference)
#include <cuda_runtime.h>

#define N_NODES  50000
#define N_EDGES  800000
#define IN_DIM   128
#define HID      64
#define OUT_DIM  128
#define N_GRAPHS 128
#define NH       (N_NODES * HID)   // 3,200,000 floats

// Scratch: h0 | h1 | pool | cnt | counts | row_ptr | cursor | col_src
__device__ float g_scratch[2 * NH + N_GRAPHS * OUT_DIM + N_GRAPHS
                           + 3 * N_NODES + 8 + N_EDGES];

using u64 = unsigned long long;

// ---- packed f32x2 helpers (Blackwell FFMA2 — PTX-only) --------------------
__device__ __forceinline__ u64 pack2(float x, float y) {
    u64 r; asm("mov.b64 %0, {%1, %2};" : "=l"(r) : "f"(x), "f"(y)); return r;
}
__device__ __forceinline__ u64 pack2s(float s) {
    u64 r; asm("mov.b64 %0, {%1, %1};" : "=l"(r) : "f"(s)); return r;
}
__device__ __forceinline__ void ffma2(u64& a, u64 s, u64 w) {
    asm("fma.rn.f32x2 %0, %1, %2, %3;" : "=l"(a) : "l"(s), "l"(w), "l"(a));
}
__device__ __forceinline__ float2 unpack2(u64 v) {
    float2 f; asm("mov.b64 {%0, %1}, %2;" : "=f"(f.x), "=f"(f.y) : "l"(v));
    return f;
}

struct Acc4 { u64 lo, hi; };

__device__ __forceinline__ Acc4 acc_init(float4 b) {
    Acc4 a; a.lo = pack2(b.x, b.y); a.hi = pack2(b.z, b.w); return a;
}
__device__ __forceinline__ void fma2x2(Acc4& a, u64 s2, ulonglong2 w) {
    ffma2(a.lo, s2, w.x);
    ffma2(a.hi, s2, w.y);
}
__device__ __forceinline__ float4 acc_to_f4(Acc4 a) {
    float2 l = unpack2(a.lo), h = unpack2(a.hi);
    return make_float4(l.x, l.y, h.x, h.y);
}
__device__ __forceinline__ float4 relu4(float4 v) {
    v.x = fmaxf(v.x, 0.f); v.y = fmaxf(v.y, 0.f);
    v.z = fmaxf(v.z, 0.f); v.w = fmaxf(v.w, 0.f);
    return v;
}

// ---------------------------------------------------------------------------
// Zero pool | cnt | counts (contiguous, word-count divisible by 4).
// ---------------------------------------------------------------------------
__global__ void zero_small_kernel(float* __restrict__ p, int n4) {
    const float4 z = make_float4(0.f, 0.f, 0.f, 0.f);
    int i = blockIdx.x * blockDim.x + threadIdx.x;
    for (int j = i; j < n4; j += gridDim.x * blockDim.x)
        ((float4*)p)[j] = z;
}

// ---------------------------------------------------------------------------
// CSR build: histogram by dst, exclusive scan, fill src lists.
// ---------------------------------------------------------------------------
__global__ void hist_kernel(const int* __restrict__ ei, int* __restrict__ counts,
                            int n_edges) {
    int i = blockIdx.x * blockDim.x + threadIdx.x;
    for (; i < n_edges; i += gridDim.x * blockDim.x)
        atomicAdd(&counts[ei[n_edges + i]], 1);
}

__global__ void scan_kernel(const int* __restrict__ counts,
                            int* __restrict__ row_ptr,
                            int* __restrict__ cursor) {
    __shared__ int part[1024];
    const int tid = threadIdx.x;
    const int CH = (N_NODES + 1023) / 1024;  // 49
    const int b = tid * CH;
    int s = 0;
    for (int j = 0; j < CH; j++) {
        int idx = b + j;
        if (idx < N_NODES) s += counts[idx];
    }
    part[tid] = s;
    __syncthreads();
    for (int off = 1; off < 1024; off <<= 1) {
        int v = (tid >= off) ? part[tid - off] : 0;
        __syncthreads();
        part[tid] += v;
        __syncthreads();
    }
    int run = (tid == 0) ? 0 : part[tid - 1];
    for (int j = 0; j < CH; j++) {
        int idx = b + j;
        if (idx < N_NODES) {
            row_ptr[idx] = run;
            cursor[idx]  = run;
            run += counts[idx];
        }
    }
    if (tid == 1023) row_ptr[N_NODES] = part[1023];
}

__global__ void fill_kernel(const int* __restrict__ ei, int* __restrict__ cursor,
                            int* __restrict__ col_src, int n_edges) {
    int i = blockIdx.x * blockDim.x + threadIdx.x;
    for (; i < n_edges; i += gridDim.x * blockDim.x) {
        int dst = ei[n_edges + i];
        int pos = atomicAdd(&cursor[dst], 1);
        col_src[pos] = ei[i];
    }
}

// ---------------------------------------------------------------------------
// proj_in: out[n, 0:64] = x[n, 0:128] @ W[128,64] + b
// 256 threads: 16 col-groups (4 cols) x 16 slots (4 nodes) = 64 nodes/iter.
// ---------------------------------------------------------------------------
__global__ void proj_in_kernel(const float* __restrict__ x,
                               const float* __restrict__ W,
                               const float* __restrict__ b,
                               float* __restrict__ out) {
    extern __shared__ float sh[];
    float* wsh = sh;                 // 128*64 floats
    float* xsh = sh + IN_DIM * HID;  // 64*128 floats
    const int tid = threadIdx.x;

    for (int i = tid; i < IN_DIM * HID / 4; i += 256)
        ((float4*)wsh)[i] = ((const float4*)W)[i];

    const int cg   = tid & 15;
    const int slot = tid >> 4;
    const float4 b4 = ((const float4*)b)[cg];

    for (int base = blockIdx.x * 64; base < N_NODES; base += gridDim.x * 64) {
        __syncthreads();
        for (int i = tid; i < 64 * IN_DIM / 4; i += 256) {
            int node = base + (i >> 5);
            float4 v = make_float4(0.f, 0.f, 0.f, 0.f);
            if (node < N_NODES)
                v = ((const float4*)x)[node * (IN_DIM / 4) + (i & 31)];
            ((float4*)xsh)[i] = v;
        }
        __syncthreads();

        Acc4 a0 = acc_init(b4), a1 = a0, a2 = a0, a3 = a0;
        const float4* t0 = (const float4*)(xsh + (slot * 4 + 0) * IN_DIM);
        const float4* t1 = (const float4*)(xsh + (slot * 4 + 1) * IN_DIM);
        const float4* t2 = (const float4*)(xsh + (slot * 4 + 2) * IN_DIM);
        const float4* t3 = (const float4*)(xsh + (slot * 4 + 3) * IN_DIM);
#pragma unroll 4
        for (int k4 = 0; k4 < IN_DIM / 4; k4++) {
            float4 s0 = t0[k4], s1 = t1[k4], s2 = t2[k4], s3 = t3[k4];
#pragma unroll
            for (int j = 0; j < 4; j++) {
                ulonglong2 w = ((const ulonglong2*)wsh)[(k4 * 4 + j) * 16 + cg];
                fma2x2(a0, pack2s(((const float*)&s0)[j]), w);
                fma2x2(a1, pack2s(((const float*)&s1)[j]), w);
                fma2x2(a2, pack2s(((const float*)&s2)[j]), w);
                fma2x2(a3, pack2s(((const float*)&s3)[j]), w);
            }
        }
        int node = base + slot * 4;
        if (node + 0 < N_NODES) ((float4*)(out + (node + 0) * HID))[cg] = acc_to_f4(a0);
        if (node + 1 < N_NODES) ((float4*)(out + (node + 1) * HID))[cg] = acc_to_f4(a1);
        if (node + 2 < N_NODES) ((float4*)(out + (node + 2) * HID))[cg] = acc_to_f4(a2);
        if (node + 3 < N_NODES) ((float4*)(out + (node + 3) * HID))[cg] = acc_to_f4(a3);
    }
}

// ---------------------------------------------------------------------------
// Fused GIN conv: t[n] = hin[n] + sum_{e: dst(e)=n} hin[src(e)]  (CSR gather)
//                 z = relu(t@W1+b1); out = relu(z@W2+b2)   [outer conv relu]
// 256 threads: 16 col-groups x 16 slots x 4 nodes = 64 nodes/iter.
// ---------------------------------------------------------------------------
__global__ void __launch_bounds__(256, 4)
gin_mlp_fused_kernel(const float* __restrict__ hin,
                     const int* __restrict__ row_ptr,
                     const int* __restrict__ col_src,
                     const float* __restrict__ W1,
                     const float* __restrict__ b1,
                     const float* __restrict__ W2,
                     const float* __restrict__ b2,
                     float* __restrict__ hout) {
    __shared__ float w1sh[HID * HID];
    __shared__ float w2sh[HID * HID];
    __shared__ float tsh[64 * HID];
    const int tid = threadIdx.x;

    for (int i = tid; i < HID * HID / 4; i += 256) {
        ((float4*)w1sh)[i] = ((const float4*)W1)[i];
        ((float4*)w2sh)[i] = ((const float4*)W2)[i];
    }

    const int cg   = tid & 15;
    const int slot = tid >> 4;
    const float4 b14 = ((const float4*)b1)[cg];
    const float4 b24 = ((const float4*)b2)[cg];

    for (int base = blockIdx.x * 64; base < N_NODES; base += gridDim.x * 64) {
        __syncthreads();
        // Gather phase: t = hin[node] + sum over in-edges (coalesced row reads)
#pragma unroll
        for (int j = 0; j < 4; j++) {
            int node = base + slot * 4 + j;
            float4 acc = make_float4(0.f, 0.f, 0.f, 0.f);
            if (node < N_NODES) {
                acc = ((const float4*)hin)[node * (HID / 4) + cg];
                int e   = __ldg(row_ptr + node);
                int end = __ldg(row_ptr + node + 1);
                for (; e < end; e++) {
                    int src = __ldg(col_src + e);
                    float4 v = ((const float4*)hin)[src * (HID / 4) + cg];
                    acc.x += v.x; acc.y += v.y; acc.z += v.z; acc.w += v.w;
                }
            }
            ((float4*)tsh)[(slot * 4 + j) * 16 + cg] = acc;
        }
        __syncthreads();

        const float4* t0 = (const float4*)(tsh + (slot * 4 + 0) * HID);
        const float4* t1 = (const float4*)(tsh + (slot * 4 + 1) * HID);
        const float4* t2 = (const float4*)(tsh + (slot * 4 + 2) * HID);
        const float4* t3 = (const float4*)(tsh + (slot * 4 + 3) * HID);

        // GEMV 1
        Acc4 z0 = acc_init(b14), z1 = z0, z2 = z0, z3 = z0;
#pragma unroll 4
        for (int k4 = 0; k4 < HID / 4; k4++) {
            float4 s0 = t0[k4], s1 = t1[k4], s2 = t2[k4], s3 = t3[k4];
#pragma unroll
            for (int j = 0; j < 4; j++) {
                ulonglong2 w = ((const ulonglong2*)w1sh)[(k4 * 4 + j) * 16 + cg];
                fma2x2(z0, pack2s(((const float*)&s0)[j]), w);
                fma2x2(z1, pack2s(((const float*)&s1)[j]), w);
                fma2x2(z2, pack2s(((const float*)&s2)[j]), w);
                fma2x2(z3, pack2s(((const float*)&s3)[j]), w);
            }
        }
        float4 zf0 = relu4(acc_to_f4(z0));
        float4 zf1 = relu4(acc_to_f4(z1));
        float4 zf2 = relu4(acc_to_f4(z2));
        float4 zf3 = relu4(acc_to_f4(z3));

        __syncthreads();  // all reads of tsh complete
        ((float4*)tsh)[(slot * 4 + 0) * 16 + cg] = zf0;
        ((float4*)tsh)[(slot * 4 + 1) * 16 + cg] = zf1;
        ((float4*)tsh)[(slot * 4 + 2) * 16 + cg] = zf2;
        ((float4*)tsh)[(slot * 4 + 3) * 16 + cg] = zf3;
        __syncthreads();

        // GEMV 2
        Acc4 o0 = acc_init(b24), o1 = o0, o2 = o0, o3 = o0;
#pragma unroll 4
        for (int k4 = 0; k4 < HID / 4; k4++) {
            float4 s0 = t0[k4], s1 = t1[k4], s2 = t2[k4], s3 = t3[k4];
#pragma unroll
            for (int j = 0; j < 4; j++) {
                ulonglong2 w = ((const ulonglong2*)w2sh)[(k4 * 4 + j) * 16 + cg];
                fma2x2(o0, pack2s(((const float*)&s0)[j]), w);
                fma2x2(o1, pack2s(((const float*)&s1)[j]), w);
                fma2x2(o2, pack2s(((const float*)&s2)[j]), w);
                fma2x2(o3, pack2s(((const float*)&s3)[j]), w);
            }
        }
        int node = base + slot * 4;
        if (node + 0 < N_NODES) ((float4*)(hout + (node + 0) * HID))[cg] = relu4(acc_to_f4(o0));
        if (node + 1 < N_NODES) ((float4*)(hout + (node + 1) * HID))[cg] = relu4(acc_to_f4(o1));
        if (node + 2 < N_NODES) ((float4*)(hout + (node + 2) * HID))[cg] = relu4(acc_to_f4(o2));
        if (node + 3 < N_NODES) ((float4*)(hout + (node + 3) * HID))[cg] = relu4(acc_to_f4(o3));
    }
}

// ---------------------------------------------------------------------------
// proj_out + global mean pool accumulation.
// 256 threads: 32 col-groups (4 cols) x 8 slots x 4 nodes = 32 nodes/iter.
// ---------------------------------------------------------------------------
__global__ void proj_out_pool_kernel(const float* __restrict__ h,
                                     const int* __restrict__ batch,
                                     const float* __restrict__ W,
                                     const float* __restrict__ b,
                                     float* __restrict__ pool,
                                     float* __restrict__ cnt) {
    __shared__ float wsh[HID * OUT_DIM];  // 32KB
    __shared__ float hsh[32 * HID];       // 8KB
    const int tid = threadIdx.x;

    for (int i = tid; i < HID * OUT_DIM / 4; i += 256)
        ((float4*)wsh)[i] = ((const float4*)W)[i];

    const int cg   = tid & 31;
    const int slot = tid >> 5;
    const float4 b4 = ((const float4*)b)[cg];

    for (int base = blockIdx.x * 32; base < N_NODES; base += gridDim.x * 32) {
        __syncthreads();
        for (int i = tid; i < 32 * HID / 4; i += 256) {
            int node = base + (i >> 4);
            float4 v = make_float4(0.f, 0.f, 0.f, 0.f);
            if (node < N_NODES)
                v = ((const float4*)h)[node * (HID / 4) + (i & 15)];
            ((float4*)hsh)[i] = v;
        }
        __syncthreads();

        Acc4 a0 = acc_init(b4), a1 = a0, a2 = a0, a3 = a0;
        const float4* t0 = (const float4*)(hsh + (slot * 4 + 0) * HID);
        const float4* t1 = (const float4*)(hsh + (slot * 4 + 1) * HID);
        const float4* t2 = (const float4*)(hsh + (slot * 4 + 2) * HID);
        const float4* t3 = (const float4*)(hsh + (slot * 4 + 3) * HID);
#pragma unroll 4
        for (int k4 = 0; k4 < HID / 4; k4++) {
            float4 s0 = t0[k4], s1 = t1[k4], s2 = t2[k4], s3 = t3[k4];
#pragma unroll
            for (int j = 0; j < 4; j++) {
                ulonglong2 w = ((const ulonglong2*)wsh)[(k4 * 4 + j) * 32 + cg];
                fma2x2(a0, pack2s(((const float*)&s0)[j]), w);
                fma2x2(a1, pack2s(((const float*)&s1)[j]), w);
                fma2x2(a2, pack2s(((const float*)&s2)[j]), w);
                fma2x2(a3, pack2s(((const float*)&s3)[j]), w);
            }
        }

        int node = base + slot * 4;
#pragma unroll
        for (int j = 0; j < 4; j++) {
            int n = node + j;
            if (n < N_NODES) {
                float4 a = acc_to_f4(j == 0 ? a0 : j == 1 ? a1 : j == 2 ? a2 : a3);
                int g = batch[n];
                float* addr = pool + g * OUT_DIM + cg * 4;
                asm volatile("red.global.add.v4.f32 [%0], {%1, %2, %3, %4};"
                             :: "l"(addr), "f"(a.x), "f"(a.y), "f"(a.z), "f"(a.w)
                             : "memory");
                if (cg == 0)
                    atomicAdd(cnt + g, 1.0f);
            }
        }
    }
}

// ---------------------------------------------------------------------------
__global__ void finalize_kernel(const float* __restrict__ pool,
                                const float* __restrict__ cnt,
                                float* __restrict__ out) {
    int i = blockIdx.x * blockDim.x + threadIdx.x;
    if (i < N_GRAPHS * OUT_DIM)
        out[i] = pool[i] / fmaxf(cnt[i >> 7], 1.0f);
}

// ---------------------------------------------------------------------------
extern "C" void kernel_launch(void* const* d_in, const int* in_sizes, int n_in,
                              void* d_out, int out_size) {
    const float* x     = (const float*)d_in[0];
    const int*   ei    = (const int*)d_in[1];   // [2, E] int32
    const int*   batch = (const int*)d_in[2];   // [N] int32
    const float* W_in  = (const float*)d_in[3];
    const float* b_in  = (const float*)d_in[4];
    const float* W1_0  = (const float*)d_in[5];
    const float* b1_0  = (const float*)d_in[6];
    const float* W2_0  = (const float*)d_in[7];
    const float* b2_0  = (const float*)d_in[8];
    const float* W1_1  = (const float*)d_in[9];
    const float* b1_1  = (const float*)d_in[10];
    const float* W2_1  = (const float*)d_in[11];
    const float* b2_1  = (const float*)d_in[12];
    const float* W_out = (const float*)d_in[13];
    const float* b_out = (const float*)d_in[14];
    const int n_edges  = in_sizes[1] / 2;
    float* out = (float*)d_out;

    void* basep = nullptr;
    cudaGetSymbolAddress(&basep, g_scratch);
    float* h0      = (float*)basep;
    float* h1      = h0 + NH;
    float* pool    = h1 + NH;
    float* cnt     = pool + N_GRAPHS * OUT_DIM;
    int*   counts  = (int*)(cnt + N_GRAPHS);
    int*   row_ptr = counts + N_NODES;
    int*   cursor  = row_ptr + N_NODES + 2;
    int*   col_src = cursor + N_NODES;

    // zero pool | cnt | counts (contiguous; 66512 words, /4 exact)
    const int zero_n4 = (N_GRAPHS * OUT_DIM + N_GRAPHS + N_NODES) / 4;
    zero_small_kernel<<<64, 256>>>(pool, zero_n4);

    // CSR build (reused by both convs)
    hist_kernel<<<400, 256>>>(ei, counts, n_edges);
    scan_kernel<<<1, 1024>>>(counts, row_ptr, cursor);
    fill_kernel<<<400, 256>>>(ei, cursor, col_src, n_edges);

    cudaFuncSetAttribute(proj_in_kernel,
                         cudaFuncAttributeMaxDynamicSharedMemorySize, 65536);
    const int g64 = (N_NODES + 63) / 64;
    const int g32 = (N_NODES + 31) / 32;

    proj_in_kernel<<<g64, 256, 65536>>>(x, W_in, b_in, h0);
    gin_mlp_fused_kernel<<<g64, 256>>>(h0, row_ptr, col_src,
                                       W1_0, b1_0, W2_0, b2_0, h1);
    gin_mlp_fused_kernel<<<g64, 256>>>(h1, row_ptr, col_src,
                                       W1_1, b1_1, W2_1, b2_1, h0);
    proj_out_pool_kernel<<<g32, 256>>>(h0, batch, W_out, b_out, pool, cnt);
    finalize_kernel<<<(N_GRAPHS * OUT_DIM + 255) / 256, 256>>>(pool, cnt, out);
}

// round 7
// speedup vs baseline: 1.1744x; 1.1744x over previous
#include <cuda_runtime.h>

#define N_NODES  50000
#define IN_DIM   128
#define HID      64
#define OUT_DIM  128
#define N_GRAPHS 128
#define NH       (N_NODES * HID)   // 3,200,000 floats

// One big scratch: h0 | h1 | agg0 | agg1 | pool_sum | pool_cnt
__device__ float g_scratch[4 * NH + N_GRAPHS * OUT_DIM + N_GRAPHS];

using u64 = unsigned long long;

// ---- packed f32x2 helpers (Blackwell FFMA2 — PTX-only) --------------------
__device__ __forceinline__ u64 pack2(float x, float y) {
    u64 r; asm("mov.b64 %0, {%1, %2};" : "=l"(r) : "f"(x), "f"(y)); return r;
}
__device__ __forceinline__ u64 pack2s(float s) {
    u64 r; asm("mov.b64 %0, {%1, %1};" : "=l"(r) : "f"(s)); return r;
}
__device__ __forceinline__ void ffma2(u64& a, u64 s, u64 w) {
    asm("fma.rn.f32x2 %0, %1, %2, %3;" : "=l"(a) : "l"(s), "l"(w), "l"(a));
}
__device__ __forceinline__ float2 unpack2(u64 v) {
    float2 f; asm("mov.b64 {%0, %1}, %2;" : "=f"(f.x), "=f"(f.y) : "l"(v));
    return f;
}

struct Acc4 { u64 lo, hi; };

__device__ __forceinline__ Acc4 acc_init(float4 b) {
    Acc4 a; a.lo = pack2(b.x, b.y); a.hi = pack2(b.z, b.w); return a;
}
__device__ __forceinline__ void fma2x2(Acc4& a, u64 s2, ulonglong2 w) {
    ffma2(a.lo, s2, w.x);
    ffma2(a.hi, s2, w.y);
}
__device__ __forceinline__ float4 acc_to_f4(Acc4 a) {
    float2 l = unpack2(a.lo), h = unpack2(a.hi);
    return make_float4(l.x, l.y, h.x, h.y);
}
__device__ __forceinline__ float4 relu4(float4 v) {
    v.x = fmaxf(v.x, 0.f); v.y = fmaxf(v.y, 0.f);
    v.z = fmaxf(v.z, 0.f); v.w = fmaxf(v.w, 0.f);
    return v;
}

// ---------------------------------------------------------------------------
// Zero the accumulator regions (agg0, agg1, pool, cnt) — contiguous.
// ---------------------------------------------------------------------------
__global__ void zero_kernel(float* __restrict__ p, int n4) {
    const float4 z = make_float4(0.f, 0.f, 0.f, 0.f);
    int i = blockIdx.x * blockDim.x + threadIdx.x;
    int stride = gridDim.x * blockDim.x;
    for (int j = i; j < n4; j += stride)
        ((float4*)p)[j] = z;
}

// ---------------------------------------------------------------------------
// proj_in: out[n, 0:64] = x[n, 0:128] @ W[128,64] + b
// 256 threads: 16 col-groups (4 cols) x 16 slots (3 nodes) = 48 nodes/iter.
// Smem: W 32KB + x-tile 24KB = 56KB -> 4 blocks/SM.
// ---------------------------------------------------------------------------
__global__ void __launch_bounds__(256, 4)
proj_in_kernel(const float* __restrict__ x,
               const float* __restrict__ W,
               const float* __restrict__ b,
               float* __restrict__ out) {
    extern __shared__ float sh[];
    float* wsh = sh;                 // 128*64 floats = 32KB
    float* xsh = sh + IN_DIM * HID;  // 48*128 floats = 24KB
    const int tid = threadIdx.x;

    for (int i = tid; i < IN_DIM * HID / 4; i += 256)
        ((float4*)wsh)[i] = ((const float4*)W)[i];

    const int cg   = tid & 15;
    const int slot = tid >> 4;
    const float4 b4 = ((const float4*)b)[cg];

    for (int base = blockIdx.x * 48; base < N_NODES; base += gridDim.x * 48) {
        __syncthreads();
        for (int i = tid; i < 48 * IN_DIM / 4; i += 256) {
            int node = base + (i >> 5);
            float4 v = make_float4(0.f, 0.f, 0.f, 0.f);
            if (node < N_NODES)
                v = ((const float4*)x)[node * (IN_DIM / 4) + (i & 31)];
            ((float4*)xsh)[i] = v;
        }
        __syncthreads();

        Acc4 a0 = acc_init(b4), a1 = a0, a2 = a0;
        const float4* t0 = (const float4*)(xsh + (slot * 3 + 0) * IN_DIM);
        const float4* t1 = (const float4*)(xsh + (slot * 3 + 1) * IN_DIM);
        const float4* t2 = (const float4*)(xsh + (slot * 3 + 2) * IN_DIM);
#pragma unroll 4
        for (int k4 = 0; k4 < IN_DIM / 4; k4++) {
            float4 s0 = t0[k4], s1 = t1[k4], s2 = t2[k4];
#pragma unroll
            for (int j = 0; j < 4; j++) {
                ulonglong2 w = ((const ulonglong2*)wsh)[(k4 * 4 + j) * 16 + cg];
                fma2x2(a0, pack2s(((const float*)&s0)[j]), w);
                fma2x2(a1, pack2s(((const float*)&s1)[j]), w);
                fma2x2(a2, pack2s(((const float*)&s2)[j]), w);
            }
        }
        int node = base + slot * 3;
        if (node + 0 < N_NODES) ((float4*)(out + (node + 0) * HID))[cg] = acc_to_f4(a0);
        if (node + 1 < N_NODES) ((float4*)(out + (node + 1) * HID))[cg] = acc_to_f4(a1);
        if (node + 2 < N_NODES) ((float4*)(out + (node + 2) * HID))[cg] = acc_to_f4(a2);
    }
}

// ---------------------------------------------------------------------------
// Edge scatter-add: 16 lanes per edge, 2 edges per warp.
// Each lane moves 16B (float4) of the 256B row via red.global.add.v4.f32.
// ---------------------------------------------------------------------------
__global__ void scatter_kernel(const int* __restrict__ ei,
                               const float* __restrict__ h,
                               float* __restrict__ agg, int n_edges) {
    int idx  = blockIdx.x * blockDim.x + threadIdx.x;
    int e    = idx >> 4;
    int lane = idx & 15;
    if (e >= n_edges) return;
    int src = __ldg(ei + e);
    int dst = __ldg(ei + n_edges + e);
    float4 v = ((const float4*)(h + (long)src * HID))[lane];
    float* addr = agg + (long)dst * HID + lane * 4;
    asm volatile("red.global.add.v4.f32 [%0], {%1, %2, %3, %4};"
                 :: "l"(addr), "f"(v.x), "f"(v.y), "f"(v.z), "f"(v.w)
                 : "memory");
}

// ---------------------------------------------------------------------------
// GIN MLP: t = hin + agg; z = relu(t@W1+b1); out = relu(z@W2+b2)
// 256 threads: 16 col-groups x 16 slots x 4 nodes = 64 nodes/iter.
// Smem 48KB static -> 4 blocks/SM with launch_bounds cap at 64 regs.
// ---------------------------------------------------------------------------
__global__ void __launch_bounds__(256, 4)
gin_mlp_kernel(const float* __restrict__ hin,
               const float* __restrict__ agg,
               const float* __restrict__ W1,
               const float* __restrict__ b1,
               const float* __restrict__ W2,
               const float* __restrict__ b2,
               float* __restrict__ hout) {
    __shared__ float w1sh[HID * HID];
    __shared__ float w2sh[HID * HID];
    __shared__ float tsh[64 * HID];
    const int tid = threadIdx.x;

    for (int i = tid; i < HID * HID / 4; i += 256) {
        ((float4*)w1sh)[i] = ((const float4*)W1)[i];
        ((float4*)w2sh)[i] = ((const float4*)W2)[i];
    }

    const int cg   = tid & 15;
    const int slot = tid >> 4;
    const float4 b14 = ((const float4*)b1)[cg];
    const float4 b24 = ((const float4*)b2)[cg];

    for (int base = blockIdx.x * 64; base < N_NODES; base += gridDim.x * 64) {
        __syncthreads();
        for (int i = tid; i < 1024; i += 256) {
            int node = base + (i >> 4);
            float4 v = make_float4(0.f, 0.f, 0.f, 0.f);
            if (node < N_NODES) {
                float4 a = ((const float4*)hin)[node * (HID / 4) + (i & 15)];
                float4 g = ((const float4*)agg)[node * (HID / 4) + (i & 15)];
                v.x = a.x + g.x; v.y = a.y + g.y;
                v.z = a.z + g.z; v.w = a.w + g.w;
            }
            ((float4*)tsh)[i] = v;
        }
        __syncthreads();

        const float4* t0 = (const float4*)(tsh + (slot * 4 + 0) * HID);
        const float4* t1 = (const float4*)(tsh + (slot * 4 + 1) * HID);
        const float4* t2 = (const float4*)(tsh + (slot * 4 + 2) * HID);
        const float4* t3 = (const float4*)(tsh + (slot * 4 + 3) * HID);

        // GEMV 1
        Acc4 z0 = acc_init(b14), z1 = z0, z2 = z0, z3 = z0;
#pragma unroll 4
        for (int k4 = 0; k4 < HID / 4; k4++) {
            float4 s0 = t0[k4], s1 = t1[k4], s2 = t2[k4], s3 = t3[k4];
#pragma unroll
            for (int j = 0; j < 4; j++) {
                ulonglong2 w = ((const ulonglong2*)w1sh)[(k4 * 4 + j) * 16 + cg];
                fma2x2(z0, pack2s(((const float*)&s0)[j]), w);
                fma2x2(z1, pack2s(((const float*)&s1)[j]), w);
                fma2x2(z2, pack2s(((const float*)&s2)[j]), w);
                fma2x2(z3, pack2s(((const float*)&s3)[j]), w);
            }
        }
        float4 zf0 = relu4(acc_to_f4(z0));
        float4 zf1 = relu4(acc_to_f4(z1));
        float4 zf2 = relu4(acc_to_f4(z2));
        float4 zf3 = relu4(acc_to_f4(z3));

        __syncthreads();  // all reads of tsh complete
        ((float4*)tsh)[(slot * 4 + 0) * 16 + cg] = zf0;
        ((float4*)tsh)[(slot * 4 + 1) * 16 + cg] = zf1;
        ((float4*)tsh)[(slot * 4 + 2) * 16 + cg] = zf2;
        ((float4*)tsh)[(slot * 4 + 3) * 16 + cg] = zf3;
        __syncthreads();

        // GEMV 2
        Acc4 o0 = acc_init(b24), o1 = o0, o2 = o0, o3 = o0;
#pragma unroll 4
        for (int k4 = 0; k4 < HID / 4; k4++) {
            float4 s0 = t0[k4], s1 = t1[k4], s2 = t2[k4], s3 = t3[k4];
#pragma unroll
            for (int j = 0; j < 4; j++) {
                ulonglong2 w = ((const ulonglong2*)w2sh)[(k4 * 4 + j) * 16 + cg];
                fma2x2(o0, pack2s(((const float*)&s0)[j]), w);
                fma2x2(o1, pack2s(((const float*)&s1)[j]), w);
                fma2x2(o2, pack2s(((const float*)&s2)[j]), w);
                fma2x2(o3, pack2s(((const float*)&s3)[j]), w);
            }
        }
        int node = base + slot * 4;
        if (node + 0 < N_NODES) ((float4*)(hout + (node + 0) * HID))[cg] = relu4(acc_to_f4(o0));
        if (node + 1 < N_NODES) ((float4*)(hout + (node + 1) * HID))[cg] = relu4(acc_to_f4(o1));
        if (node + 2 < N_NODES) ((float4*)(hout + (node + 2) * HID))[cg] = relu4(acc_to_f4(o2));
        if (node + 3 < N_NODES) ((float4*)(hout + (node + 3) * HID))[cg] = relu4(acc_to_f4(o3));
    }
}

// ---------------------------------------------------------------------------
// proj_out + global mean pool accumulation.
// 256 threads: 32 col-groups (4 cols) x 8 slots x 4 nodes = 32 nodes/iter.
// Smem 40KB -> 4 blocks/SM with reg cap.
// ---------------------------------------------------------------------------
__global__ void __launch_bounds__(256, 4)
proj_out_pool_kernel(const float* __restrict__ h,
                     const int* __restrict__ batch,
                     const float* __restrict__ W,
                     const float* __restrict__ b,
                     float* __restrict__ pool,
                     float* __restrict__ cnt) {
    __shared__ float wsh[HID * OUT_DIM];  // 32KB
    __shared__ float hsh[32 * HID];       // 8KB
    const int tid = threadIdx.x;

    for (int i = tid; i < HID * OUT_DIM / 4; i += 256)
        ((float4*)wsh)[i] = ((const float4*)W)[i];

    const int cg   = tid & 31;
    const int slot = tid >> 5;
    const float4 b4 = ((const float4*)b)[cg];

    for (int base = blockIdx.x * 32; base < N_NODES; base += gridDim.x * 32) {
        __syncthreads();
        for (int i = tid; i < 32 * HID / 4; i += 256) {
            int node = base + (i >> 4);
            float4 v = make_float4(0.f, 0.f, 0.f, 0.f);
            if (node < N_NODES)
                v = ((const float4*)h)[node * (HID / 4) + (i & 15)];
            ((float4*)hsh)[i] = v;
        }
        __syncthreads();

        Acc4 a0 = acc_init(b4), a1 = a0, a2 = a0, a3 = a0;
        const float4* t0 = (const float4*)(hsh + (slot * 4 + 0) * HID);
        const float4* t1 = (const float4*)(hsh + (slot * 4 + 1) * HID);
        const float4* t2 = (const float4*)(hsh + (slot * 4 + 2) * HID);
        const float4* t3 = (const float4*)(hsh + (slot * 4 + 3) * HID);
#pragma unroll 4
        for (int k4 = 0; k4 < HID / 4; k4++) {
            float4 s0 = t0[k4], s1 = t1[k4], s2 = t2[k4], s3 = t3[k4];
#pragma unroll
            for (int j = 0; j < 4; j++) {
                ulonglong2 w = ((const ulonglong2*)wsh)[(k4 * 4 + j) * 32 + cg];
                fma2x2(a0, pack2s(((const float*)&s0)[j]), w);
                fma2x2(a1, pack2s(((const float*)&s1)[j]), w);
                fma2x2(a2, pack2s(((const float*)&s2)[j]), w);
                fma2x2(a3, pack2s(((const float*)&s3)[j]), w);
            }
        }

        int node = base + slot * 4;
#pragma unroll
        for (int j = 0; j < 4; j++) {
            int n = node + j;
            if (n < N_NODES) {
                float4 a = acc_to_f4(j == 0 ? a0 : j == 1 ? a1 : j == 2 ? a2 : a3);
                int g = batch[n];
                float* addr = pool + g * OUT_DIM + cg * 4;
                asm volatile("red.global.add.v4.f32 [%0], {%1, %2, %3, %4};"
                             :: "l"(addr), "f"(a.x), "f"(a.y), "f"(a.z), "f"(a.w)
                             : "memory");
                if (cg == 0)
                    atomicAdd(cnt + g, 1.0f);
            }
        }
    }
}

// ---------------------------------------------------------------------------
__global__ void finalize_kernel(const float* __restrict__ pool,
                                const float* __restrict__ cnt,
                                float* __restrict__ out) {
    int i = blockIdx.x * blockDim.x + threadIdx.x;
    if (i < N_GRAPHS * OUT_DIM)
        out[i] = pool[i] / fmaxf(cnt[i >> 7], 1.0f);
}

// ---------------------------------------------------------------------------
extern "C" void kernel_launch(void* const* d_in, const int* in_sizes, int n_in,
                              void* d_out, int out_size) {
    const float* x     = (const float*)d_in[0];
    const int*   ei    = (const int*)d_in[1];   // [2, E] int32
    const int*   batch = (const int*)d_in[2];   // [N] int32
    const float* W_in  = (const float*)d_in[3];
    const float* b_in  = (const float*)d_in[4];
    const float* W1_0  = (const float*)d_in[5];
    const float* b1_0  = (const float*)d_in[6];
    const float* W2_0  = (const float*)d_in[7];
    const float* b2_0  = (const float*)d_in[8];
    const float* W1_1  = (const float*)d_in[9];
    const float* b1_1  = (const float*)d_in[10];
    const float* W2_1  = (const float*)d_in[11];
    const float* b2_1  = (const float*)d_in[12];
    const float* W_out = (const float*)d_in[13];
    const float* b_out = (const float*)d_in[14];
    const int n_edges  = in_sizes[1] / 2;
    float* out = (float*)d_out;

    void* basep = nullptr;
    cudaGetSymbolAddress(&basep, g_scratch);
    float* h0   = (float*)basep;
    float* h1   = h0 + NH;
    float* a0   = h1 + NH;
    float* a1   = a0 + NH;
    float* pool = a1 + NH;
    float* cnt  = pool + N_GRAPHS * OUT_DIM;

    const int zero_n4 = (2 * NH + N_GRAPHS * OUT_DIM + N_GRAPHS) / 4;
    zero_kernel<<<512, 256>>>(a0, zero_n4);

    cudaFuncSetAttribute(proj_in_kernel,
                         cudaFuncAttributeMaxDynamicSharedMemorySize, 57344);
    const int g48 = (N_NODES + 47) / 48;
    const int g64 = (N_NODES + 63) / 64;
    const int g32 = (N_NODES + 31) / 32;
    const int ge  = (n_edges * 16 + 255) / 256;

    proj_in_kernel<<<g48, 256, 57344>>>(x, W_in, b_in, h0);
    scatter_kernel<<<ge, 256>>>(ei, h0, a0, n_edges);
    gin_mlp_kernel<<<g64, 256>>>(h0, a0, W1_0, b1_0, W2_0, b2_0, h1);
    scatter_kernel<<<ge, 256>>>(ei, h1, a1, n_edges);
    gin_mlp_kernel<<<g64, 256>>>(h1, a1, W1_1, b1_1, W2_1, b2_1, h0);
    proj_out_pool_kernel<<<g32, 256>>>(h0, batch, W_out, b_out, pool, cnt);
    finalize_kernel<<<(N_GRAPHS * OUT_DIM + 255) / 256, 256>>>(pool, cnt, out);
}

// round 8
// speedup vs baseline: 1.2191x; 1.0380x over previous
#include <cuda_runtime.h>

#define N_NODES  50000
#define IN_DIM   128
#define HID      64
#define OUT_DIM  128
#define N_GRAPHS 128
#define NH       (N_NODES * HID)   // 3,200,000 floats

// Scratch: h0 | h1 | agg0 | agg1 | pool
__device__ float g_scratch[4 * NH + N_GRAPHS * OUT_DIM + N_GRAPHS];

using u64 = unsigned long long;

// ---- packed f32x2 helpers (Blackwell FFMA2 — PTX-only) --------------------
__device__ __forceinline__ u64 pack2(float x, float y) {
    u64 r; asm("mov.b64 %0, {%1, %2};" : "=l"(r) : "f"(x), "f"(y)); return r;
}
__device__ __forceinline__ u64 pack2s(float s) {
    u64 r; asm("mov.b64 %0, {%1, %1};" : "=l"(r) : "f"(s)); return r;
}
__device__ __forceinline__ void ffma2(u64& a, u64 s, u64 w) {
    asm("fma.rn.f32x2 %0, %1, %2, %3;" : "=l"(a) : "l"(s), "l"(w), "l"(a));
}
__device__ __forceinline__ float2 unpack2(u64 v) {
    float2 f; asm("mov.b64 {%0, %1}, %2;" : "=f"(f.x), "=f"(f.y) : "l"(v));
    return f;
}

struct Acc4 { u64 lo, hi; };

__device__ __forceinline__ Acc4 acc_init(float4 b) {
    Acc4 a; a.lo = pack2(b.x, b.y); a.hi = pack2(b.z, b.w); return a;
}
__device__ __forceinline__ void fma2x2(Acc4& a, u64 s2, ulonglong2 w) {
    ffma2(a.lo, s2, w.x);
    ffma2(a.hi, s2, w.y);
}
__device__ __forceinline__ float4 acc_to_f4(Acc4 a) {
    float2 l = unpack2(a.lo), h = unpack2(a.hi);
    return make_float4(l.x, l.y, h.x, h.y);
}
__device__ __forceinline__ float4 relu4(float4 v) {
    v.x = fmaxf(v.x, 0.f); v.y = fmaxf(v.y, 0.f);
    v.z = fmaxf(v.z, 0.f); v.w = fmaxf(v.w, 0.f);
    return v;
}

// ---------------------------------------------------------------------------
// Zero the pool accumulator (pool only; agg is producer-initialized).
// ---------------------------------------------------------------------------
__global__ void zero_small_kernel(float* __restrict__ p, int n4) {
    const float4 z = make_float4(0.f, 0.f, 0.f, 0.f);
    int i = blockIdx.x * blockDim.x + threadIdx.x;
    for (int j = i; j < n4; j += gridDim.x * blockDim.x)
        ((float4*)p)[j] = z;
}

// ---------------------------------------------------------------------------
// proj_in: h = x @ W[128,64] + b ; writes h AND agg-init (= h).
// 48 nodes/block. Warp w stages rows 6w..6w+5 (warp-local); GEMV threads
// (cg = tid&15, slot = tid>>4) read rows slot*3..+2, slot in {2w, 2w+1}.
// Only ONE __syncthreads (weights).
// ---------------------------------------------------------------------------
__global__ void __launch_bounds__(256, 4)
proj_in_kernel(const float* __restrict__ x,
               const float* __restrict__ W,
               const float* __restrict__ b,
               float* __restrict__ hout,
               float* __restrict__ aggout) {
    extern __shared__ float sh[];
    float* wsh = sh;                 // 128*64 floats = 32KB
    float* xsh = sh + IN_DIM * HID;  // 48*128 floats = 24KB
    const int tid  = threadIdx.x;
    const int lane = tid & 31;
    const int warp = tid >> 5;
    const int base = blockIdx.x * 48;

    // (a) warp-local x staging: rows 6w..6w+5 (each row 32 float4)
    {
        float4* d = (float4*)(xsh + (6 * warp) * IN_DIM);
        if (base + 6 * warp + 6 <= N_NODES) {
            const float4* s = (const float4*)(x + (size_t)(base + 6 * warp) * IN_DIM);
#pragma unroll
            for (int it = 0; it < 6; it++)
                d[lane + 32 * it] = s[lane + 32 * it];
        } else {
#pragma unroll
            for (int it = 0; it < 6; it++) {
                int idx = lane + 32 * it;
                int row = idx >> 5, comp = idx & 31;
                int node = base + 6 * warp + row;
                if (node >= N_NODES) node = N_NODES - 1;
                d[row * 32 + comp] = ((const float4*)x)[(size_t)node * 32 + comp];
            }
        }
    }
    // (b) weights (overlaps with (a)'s LDG latency)
    for (int i = tid; i < IN_DIM * HID / 4; i += 256)
        ((float4*)wsh)[i] = ((const float4*)W)[i];
    __syncthreads();

    const int cg   = tid & 15;
    const int slot = tid >> 4;
    const float4 b4 = ((const float4*)b)[cg];

    Acc4 a0 = acc_init(b4), a1 = a0, a2 = a0;
    const float4* t0 = (const float4*)(xsh + (slot * 3 + 0) * IN_DIM);
    const float4* t1 = (const float4*)(xsh + (slot * 3 + 1) * IN_DIM);
    const float4* t2 = (const float4*)(xsh + (slot * 3 + 2) * IN_DIM);
#pragma unroll 4
    for (int k4 = 0; k4 < IN_DIM / 4; k4++) {
        float4 s0 = t0[k4], s1 = t1[k4], s2 = t2[k4];
#pragma unroll
        for (int j = 0; j < 4; j++) {
            ulonglong2 w = ((const ulonglong2*)wsh)[(k4 * 4 + j) * 16 + cg];
            fma2x2(a0, pack2s(((const float*)&s0)[j]), w);
            fma2x2(a1, pack2s(((const float*)&s1)[j]), w);
            fma2x2(a2, pack2s(((const float*)&s2)[j]), w);
        }
    }
    int node = base + slot * 3;
#pragma unroll
    for (int j = 0; j < 3; j++) {
        int n = node + j;
        if (n < N_NODES) {
            float4 r = acc_to_f4(j == 0 ? a0 : j == 1 ? a1 : a2);
            ((float4*)(hout + (size_t)n * HID))[cg] = r;
            ((float4*)(aggout + (size_t)n * HID))[cg] = r;
        }
    }
}

// ---------------------------------------------------------------------------
// Edge scatter-add: 16 lanes per edge, 2 edges per warp.
// agg is pre-initialized to h, so afterwards agg = h + sum(h[src]).
// ---------------------------------------------------------------------------
__global__ void scatter_kernel(const int* __restrict__ ei,
                               const float* __restrict__ h,
                               float* __restrict__ agg, int n_edges) {
    int idx  = blockIdx.x * blockDim.x + threadIdx.x;
    int e    = idx >> 4;
    int lane = idx & 15;
    if (e >= n_edges) return;
    int src = __ldg(ei + e);
    int dst = __ldg(ei + n_edges + e);
    float4 v = ((const float4*)(h + (size_t)src * HID))[lane];
    float* addr = agg + (size_t)dst * HID + lane * 4;
    asm volatile("red.global.add.v4.f32 [%0], {%1, %2, %3, %4};"
                 :: "l"(addr), "f"(v.x), "f"(v.y), "f"(v.z), "f"(v.w)
                 : "memory");
}

// ---------------------------------------------------------------------------
// GIN MLP: t = tin (already h + aggregate); z = relu(t@W1+b1);
//          out = relu(z@W2+b2); optionally also writes agg-init for next conv.
// 64 nodes/block. Warp w owns tsh rows 8w..8w+7; all phase syncs are
// __syncwarp, single __syncthreads for the weight tiles.
// ---------------------------------------------------------------------------
__global__ void __launch_bounds__(256, 4)
gin_mlp_kernel(const float* __restrict__ tin,
               const float* __restrict__ W1,
               const float* __restrict__ b1,
               const float* __restrict__ W2,
               const float* __restrict__ b2,
               float* __restrict__ hout,
               float* __restrict__ aggout) {
    __shared__ float w1sh[HID * HID];
    __shared__ float w2sh[HID * HID];
    __shared__ float tsh[64 * HID];
    const int tid  = threadIdx.x;
    const int lane = tid & 31;
    const int warp = tid >> 5;
    const int base = blockIdx.x * 64;

    // (a) warp-local t staging: rows 8w..8w+7 (each row 16 float4)
    {
        float4* d = (float4*)(tsh + (8 * warp) * HID);
        if (base + 8 * warp + 8 <= N_NODES) {
            const float4* s = (const float4*)(tin + (size_t)(base + 8 * warp) * HID);
#pragma unroll
            for (int it = 0; it < 4; it++)
                d[lane + 32 * it] = s[lane + 32 * it];
        } else {
#pragma unroll
            for (int it = 0; it < 4; it++) {
                int idx = lane + 32 * it;
                int row = idx >> 4, comp = idx & 15;
                int node = base + 8 * warp + row;
                if (node >= N_NODES) node = N_NODES - 1;
                d[row * 16 + comp] = ((const float4*)tin)[(size_t)node * 16 + comp];
            }
        }
    }
    // (b) weights
    for (int i = tid; i < HID * HID / 4; i += 256) {
        ((float4*)w1sh)[i] = ((const float4*)W1)[i];
        ((float4*)w2sh)[i] = ((const float4*)W2)[i];
    }
    __syncthreads();

    const int cg   = tid & 15;
    const int slot = tid >> 4;   // slot in {2*warp, 2*warp+1}
    const float4 b14 = ((const float4*)b1)[cg];
    const float4 b24 = ((const float4*)b2)[cg];

    const float4* t0 = (const float4*)(tsh + (slot * 4 + 0) * HID);
    const float4* t1 = (const float4*)(tsh + (slot * 4 + 1) * HID);
    const float4* t2 = (const float4*)(tsh + (slot * 4 + 2) * HID);
    const float4* t3 = (const float4*)(tsh + (slot * 4 + 3) * HID);

    // GEMV 1
    Acc4 z0 = acc_init(b14), z1 = z0, z2 = z0, z3 = z0;
#pragma unroll 4
    for (int k4 = 0; k4 < HID / 4; k4++) {
        float4 s0 = t0[k4], s1 = t1[k4], s2 = t2[k4], s3 = t3[k4];
#pragma unroll
        for (int j = 0; j < 4; j++) {
            ulonglong2 w = ((const ulonglong2*)w1sh)[(k4 * 4 + j) * 16 + cg];
            fma2x2(z0, pack2s(((const float*)&s0)[j]), w);
            fma2x2(z1, pack2s(((const float*)&s1)[j]), w);
            fma2x2(z2, pack2s(((const float*)&s2)[j]), w);
            fma2x2(z3, pack2s(((const float*)&s3)[j]), w);
        }
    }
    float4 zf0 = relu4(acc_to_f4(z0));
    float4 zf1 = relu4(acc_to_f4(z1));
    float4 zf2 = relu4(acc_to_f4(z2));
    float4 zf3 = relu4(acc_to_f4(z3));

    __syncwarp();   // warp done reading its tsh rows
    ((float4*)tsh)[(slot * 4 + 0) * 16 + cg] = zf0;
    ((float4*)tsh)[(slot * 4 + 1) * 16 + cg] = zf1;
    ((float4*)tsh)[(slot * 4 + 2) * 16 + cg] = zf2;
    ((float4*)tsh)[(slot * 4 + 3) * 16 + cg] = zf3;
    __syncwarp();   // z visible to the whole warp

    // GEMV 2
    Acc4 o0 = acc_init(b24), o1 = o0, o2 = o0, o3 = o0;
#pragma unroll 4
    for (int k4 = 0; k4 < HID / 4; k4++) {
        float4 s0 = t0[k4], s1 = t1[k4], s2 = t2[k4], s3 = t3[k4];
#pragma unroll
        for (int j = 0; j < 4; j++) {
            ulonglong2 w = ((const ulonglong2*)w2sh)[(k4 * 4 + j) * 16 + cg];
            fma2x2(o0, pack2s(((const float*)&s0)[j]), w);
            fma2x2(o1, pack2s(((const float*)&s1)[j]), w);
            fma2x2(o2, pack2s(((const float*)&s2)[j]), w);
            fma2x2(o3, pack2s(((const float*)&s3)[j]), w);
        }
    }
    int node = base + slot * 4;
#pragma unroll
    for (int j = 0; j < 4; j++) {
        int n = node + j;
        if (n < N_NODES) {
            float4 r = relu4(acc_to_f4(j == 0 ? o0 : j == 1 ? o1 : j == 2 ? o2 : o3));
            ((float4*)(hout + (size_t)n * HID))[cg] = r;
            if (aggout)
                ((float4*)(aggout + (size_t)n * HID))[cg] = r;
        }
    }
}

// ---------------------------------------------------------------------------
// proj_out + global mean pool accumulation. 32 nodes/block.
// Warp w stages rows 4w..4w+3; GEMV thread (cg = lane, slot = warp).
// ---------------------------------------------------------------------------
__global__ void __launch_bounds__(256, 4)
proj_out_pool_kernel(const float* __restrict__ h,
                     const int* __restrict__ batch,
                     const float* __restrict__ W,
                     const float* __restrict__ b,
                     float* __restrict__ pool) {
    __shared__ float wsh[HID * OUT_DIM];  // 32KB
    __shared__ float hsh[32 * HID];       // 8KB
    const int tid  = threadIdx.x;
    const int lane = tid & 31;
    const int warp = tid >> 5;
    const int base = blockIdx.x * 32;

    // (a) warp-local staging: rows 4w..4w+3 (each row 16 float4)
    {
        float4* d = (float4*)(hsh + (4 * warp) * HID);
        if (base + 4 * warp + 4 <= N_NODES) {
            const float4* s = (const float4*)(h + (size_t)(base + 4 * warp) * HID);
#pragma unroll
            for (int it = 0; it < 2; it++)
                d[lane + 32 * it] = s[lane + 32 * it];
        } else {
#pragma unroll
            for (int it = 0; it < 2; it++) {
                int idx = lane + 32 * it;
                int row = idx >> 4, comp = idx & 15;
                int node = base + 4 * warp + row;
                if (node >= N_NODES) node = N_NODES - 1;
                d[row * 16 + comp] = ((const float4*)h)[(size_t)node * 16 + comp];
            }
        }
    }
    // (b) weights
    for (int i = tid; i < HID * OUT_DIM / 4; i += 256)
        ((float4*)wsh)[i] = ((const float4*)W)[i];
    __syncthreads();

    const int cg   = lane;   // 32 col-groups of 4 cols
    const int slot = warp;   // 8 slots of 4 nodes
    const float4 b4 = ((const float4*)b)[cg];

    Acc4 a0 = acc_init(b4), a1 = a0, a2 = a0, a3 = a0;
    const float4* t0 = (const float4*)(hsh + (slot * 4 + 0) * HID);
    const float4* t1 = (const float4*)(hsh + (slot * 4 + 1) * HID);
    const float4* t2 = (const float4*)(hsh + (slot * 4 + 2) * HID);
    const float4* t3 = (const float4*)(hsh + (slot * 4 + 3) * HID);
#pragma unroll 4
    for (int k4 = 0; k4 < HID / 4; k4++) {
        float4 s0 = t0[k4], s1 = t1[k4], s2 = t2[k4], s3 = t3[k4];
#pragma unroll
        for (int j = 0; j < 4; j++) {
            ulonglong2 w = ((const ulonglong2*)wsh)[(k4 * 4 + j) * 32 + cg];
            fma2x2(a0, pack2s(((const float*)&s0)[j]), w);
            fma2x2(a1, pack2s(((const float*)&s1)[j]), w);
            fma2x2(a2, pack2s(((const float*)&s2)[j]), w);
            fma2x2(a3, pack2s(((const float*)&s3)[j]), w);
        }
    }

    int node = base + slot * 4;
#pragma unroll
    for (int j = 0; j < 4; j++) {
        int n = node + j;
        if (n < N_NODES) {
            float4 a = acc_to_f4(j == 0 ? a0 : j == 1 ? a1 : j == 2 ? a2 : a3);
            int g = __ldg(batch + n);
            float* addr = pool + g * OUT_DIM + cg * 4;
            asm volatile("red.global.add.v4.f32 [%0], {%1, %2, %3, %4};"
                         :: "l"(addr), "f"(a.x), "f"(a.y), "f"(a.z), "f"(a.w)
                         : "memory");
        }
    }
}

// ---------------------------------------------------------------------------
// finalize: counts via binary search on sorted batch (no atomics).
// ---------------------------------------------------------------------------
__global__ void finalize_kernel(const float* __restrict__ pool,
                                const int* __restrict__ batch,
                                float* __restrict__ out) {
    int i = blockIdx.x * blockDim.x + threadIdx.x;
    if (i >= N_GRAPHS * OUT_DIM) return;
    int g = i >> 7;
    int lo = 0, hi = N_NODES;
    while (lo < hi) { int m = (lo + hi) >> 1; if (__ldg(batch + m) <  g) lo = m + 1; else hi = m; }
    int start = lo;
    lo = 0; hi = N_NODES;
    while (lo < hi) { int m = (lo + hi) >> 1; if (__ldg(batch + m) <= g) lo = m + 1; else hi = m; }
    float c = (float)(lo - start);
    out[i] = pool[i] / fmaxf(c, 1.0f);
}

// ---------------------------------------------------------------------------
extern "C" void kernel_launch(void* const* d_in, const int* in_sizes, int n_in,
                              void* d_out, int out_size) {
    const float* x     = (const float*)d_in[0];
    const int*   ei    = (const int*)d_in[1];   // [2, E] int32
    const int*   batch = (const int*)d_in[2];   // [N] int32
    const float* W_in  = (const float*)d_in[3];
    const float* b_in  = (const float*)d_in[4];
    const float* W1_0  = (const float*)d_in[5];
    const float* b1_0  = (const float*)d_in[6];
    const float* W2_0  = (const float*)d_in[7];
    const float* b2_0  = (const float*)d_in[8];
    const float* W1_1  = (const float*)d_in[9];
    const float* b1_1  = (const float*)d_in[10];
    const float* W2_1  = (const float*)d_in[11];
    const float* b2_1  = (const float*)d_in[12];
    const float* W_out = (const float*)d_in[13];
    const float* b_out = (const float*)d_in[14];
    const int n_edges  = in_sizes[1] / 2;
    float* out = (float*)d_out;

    void* basep = nullptr;
    cudaGetSymbolAddress(&basep, g_scratch);
    float* h0   = (float*)basep;
    float* h1   = h0 + NH;
    float* a0   = h1 + NH;
    float* a1   = a0 + NH;
    float* pool = a1 + NH;

    // zero pool only (agg buffers are producer-initialized)
    zero_small_kernel<<<16, 256>>>(pool, N_GRAPHS * OUT_DIM / 4);

    cudaFuncSetAttribute(proj_in_kernel,
                         cudaFuncAttributeMaxDynamicSharedMemorySize, 57344);
    const int g48 = (N_NODES + 47) / 48;
    const int g64 = (N_NODES + 63) / 64;
    const int g32 = (N_NODES + 31) / 32;
    const int ge  = (n_edges * 16 + 255) / 256;

    proj_in_kernel<<<g48, 256, 57344>>>(x, W_in, b_in, h0, a0);
    scatter_kernel<<<ge, 256>>>(ei, h0, a0, n_edges);
    gin_mlp_kernel<<<g64, 256>>>(a0, W1_0, b1_0, W2_0, b2_0, h1, a1);
    scatter_kernel<<<ge, 256>>>(ei, h1, a1, n_edges);
    gin_mlp_kernel<<<g64, 256>>>(a1, W1_1, b1_1, W2_1, b2_1, h0, nullptr);
    proj_out_pool_kernel<<<g32, 256>>>(h0, batch, W_out, b_out, pool);
    finalize_kernel<<<(N_GRAPHS * OUT_DIM + 255) / 256, 256>>>(pool, batch, out);
}

// round 9
// speedup vs baseline: 1.2763x; 1.0469x over previous
#include <cuda_runtime.h>

#define N_NODES  50000
#define IN_DIM   128
#define HID      64
#define OUT_DIM  128
#define N_GRAPHS 128
#define NH       (N_NODES * HID)   // 3,200,000 floats

// Scratch: h0 | h1 | agg0 | agg1 | pool
__device__ float g_scratch[4 * NH + N_GRAPHS * OUT_DIM + N_GRAPHS];

using u64 = unsigned long long;

// ---- packed f32x2 helpers (Blackwell FFMA2 — PTX-only) --------------------
__device__ __forceinline__ u64 pack2(float x, float y) {
    u64 r; asm("mov.b64 %0, {%1, %2};" : "=l"(r) : "f"(x), "f"(y)); return r;
}
__device__ __forceinline__ u64 pack2s(float s) {
    u64 r; asm("mov.b64 %0, {%1, %1};" : "=l"(r) : "f"(s)); return r;
}
__device__ __forceinline__ void ffma2(u64& a, u64 s, u64 w) {
    asm("fma.rn.f32x2 %0, %1, %2, %3;" : "=l"(a) : "l"(s), "l"(w), "l"(a));
}
__device__ __forceinline__ float2 unpack2(u64 v) {
    float2 f; asm("mov.b64 {%0, %1}, %2;" : "=f"(f.x), "=f"(f.y) : "l"(v));
    return f;
}

struct Acc4 { u64 lo, hi; };

__device__ __forceinline__ Acc4 acc_init(float4 b) {
    Acc4 a; a.lo = pack2(b.x, b.y); a.hi = pack2(b.z, b.w); return a;
}
__device__ __forceinline__ void fma2x2(Acc4& a, u64 s2, ulonglong2 w) {
    ffma2(a.lo, s2, w.x);
    ffma2(a.hi, s2, w.y);
}
__device__ __forceinline__ float4 acc_to_f4(Acc4 a) {
    float2 l = unpack2(a.lo), h = unpack2(a.hi);
    return make_float4(l.x, l.y, h.x, h.y);
}
__device__ __forceinline__ float4 relu4(float4 v) {
    v.x = fmaxf(v.x, 0.f); v.y = fmaxf(v.y, 0.f);
    v.z = fmaxf(v.z, 0.f); v.w = fmaxf(v.w, 0.f);
    return v;
}

// ---------------------------------------------------------------------------
__global__ void zero_small_kernel(float* __restrict__ p, int n4) {
    const float4 z = make_float4(0.f, 0.f, 0.f, 0.f);
    int i = blockIdx.x * blockDim.x + threadIdx.x;
    for (int j = i; j < n4; j += gridDim.x * blockDim.x)
        ((float4*)p)[j] = z;
}

// ---------------------------------------------------------------------------
// proj_in: h = x @ W[128,64] + b ; writes h AND agg-init (= h).
// 48 nodes/block, 3 rows x 4 cols per thread (unchanged from R8).
// ---------------------------------------------------------------------------
__global__ void __launch_bounds__(256, 4)
proj_in_kernel(const float* __restrict__ x,
               const float* __restrict__ W,
               const float* __restrict__ b,
               float* __restrict__ hout,
               float* __restrict__ aggout) {
    extern __shared__ float sh[];
    float* wsh = sh;                 // 128*64 floats = 32KB
    float* xsh = sh + IN_DIM * HID;  // 48*128 floats = 24KB
    const int tid  = threadIdx.x;
    const int lane = tid & 31;
    const int warp = tid >> 5;
    const int base = blockIdx.x * 48;

    {
        float4* d = (float4*)(xsh + (6 * warp) * IN_DIM);
        if (base + 6 * warp + 6 <= N_NODES) {
            const float4* s = (const float4*)(x + (size_t)(base + 6 * warp) * IN_DIM);
#pragma unroll
            for (int it = 0; it < 6; it++)
                d[lane + 32 * it] = s[lane + 32 * it];
        } else {
#pragma unroll
            for (int it = 0; it < 6; it++) {
                int idx = lane + 32 * it;
                int row = idx >> 5, comp = idx & 31;
                int node = base + 6 * warp + row;
                if (node >= N_NODES) node = N_NODES - 1;
                d[row * 32 + comp] = ((const float4*)x)[(size_t)node * 32 + comp];
            }
        }
    }
    for (int i = tid; i < IN_DIM * HID / 4; i += 256)
        ((float4*)wsh)[i] = ((const float4*)W)[i];
    __syncthreads();

    const int cg   = tid & 15;
    const int slot = tid >> 4;
    const float4 b4 = ((const float4*)b)[cg];

    Acc4 a0 = acc_init(b4), a1 = a0, a2 = a0;
    const float4* t0 = (const float4*)(xsh + (slot * 3 + 0) * IN_DIM);
    const float4* t1 = (const float4*)(xsh + (slot * 3 + 1) * IN_DIM);
    const float4* t2 = (const float4*)(xsh + (slot * 3 + 2) * IN_DIM);
#pragma unroll 4
    for (int k4 = 0; k4 < IN_DIM / 4; k4++) {
        float4 s0 = t0[k4], s1 = t1[k4], s2 = t2[k4];
#pragma unroll
        for (int j = 0; j < 4; j++) {
            ulonglong2 w = ((const ulonglong2*)wsh)[(k4 * 4 + j) * 16 + cg];
            fma2x2(a0, pack2s(((const float*)&s0)[j]), w);
            fma2x2(a1, pack2s(((const float*)&s1)[j]), w);
            fma2x2(a2, pack2s(((const float*)&s2)[j]), w);
        }
    }
    int node = base + slot * 3;
#pragma unroll
    for (int j = 0; j < 3; j++) {
        int n = node + j;
        if (n < N_NODES) {
            float4 r = acc_to_f4(j == 0 ? a0 : j == 1 ? a1 : a2);
            ((float4*)(hout + (size_t)n * HID))[cg] = r;
            ((float4*)(aggout + (size_t)n * HID))[cg] = r;
        }
    }
}

// ---------------------------------------------------------------------------
// Edge scatter-add: 16 lanes per edge (float4 per lane), red.global.add.v4.
// ---------------------------------------------------------------------------
__global__ void scatter_kernel(const int* __restrict__ ei,
                               const float* __restrict__ h,
                               float* __restrict__ agg, int n_edges) {
    int idx  = blockIdx.x * blockDim.x + threadIdx.x;
    int e    = idx >> 4;
    int lane = idx & 15;
    if (e >= n_edges) return;
    int src = __ldg(ei + e);
    int dst = __ldg(ei + n_edges + e);
    float4 v = ((const float4*)(h + (size_t)src * HID))[lane];
    float* addr = agg + (size_t)dst * HID + lane * 4;
    asm volatile("red.global.add.v4.f32 [%0], {%1, %2, %3, %4};"
                 :: "l"(addr), "f"(v.x), "f"(v.y), "f"(v.z), "f"(v.w)
                 : "memory");
}

// ---------------------------------------------------------------------------
// GIN MLP v2: 128 nodes/block, 8 rows x 4 cols per thread.
// cg = tid&15, slot = tid>>4; slot owns rows slot*8..slot*8+7.
// Warp w stages rows 16w..16w+15 (its two slots). Weights loaded once per k4
// and reused across two 4-row halves -> 1 weight LDS per 16 FFMA2 per k.
// Smem: w1 16KB + w2 16KB + t 32KB = 64KB -> 3 blocks/SM.
// ---------------------------------------------------------------------------
__global__ void __launch_bounds__(256, 3)
gin_mlp_kernel(const float* __restrict__ tin,
               const float* __restrict__ W1,
               const float* __restrict__ b1,
               const float* __restrict__ W2,
               const float* __restrict__ b2,
               float* __restrict__ hout,
               float* __restrict__ aggout) {
    __shared__ float w1sh[HID * HID];
    __shared__ float w2sh[HID * HID];
    __shared__ float tsh[128 * HID];
    const int tid  = threadIdx.x;
    const int lane = tid & 31;
    const int warp = tid >> 5;
    const int base = blockIdx.x * 128;

    // (a) warp-local staging: rows 16w..16w+15 (each row 16 float4; 8/lane)
    {
        float4* d = (float4*)(tsh + (16 * warp) * HID);
        int rb = base + 16 * warp;
        if (rb + 16 <= N_NODES) {
            const float4* s = (const float4*)(tin + (size_t)rb * HID);
#pragma unroll
            for (int it = 0; it < 8; it++)
                d[lane + 32 * it] = s[lane + 32 * it];
        } else {
#pragma unroll
            for (int it = 0; it < 8; it++) {
                int idx = lane + 32 * it;
                int row = idx >> 4, comp = idx & 15;
                int node = rb + row;
                if (node >= N_NODES) node = N_NODES - 1;
                d[row * 16 + comp] = ((const float4*)tin)[(size_t)node * 16 + comp];
            }
        }
    }
    // (b) weights
    for (int i = tid; i < HID * HID / 4; i += 256) {
        ((float4*)w1sh)[i] = ((const float4*)W1)[i];
        ((float4*)w2sh)[i] = ((const float4*)W2)[i];
    }
    __syncthreads();

    const int cg   = tid & 15;
    const int slot = tid >> 4;
    const float* trow = tsh + (size_t)slot * 8 * HID;
    const float4 b14 = ((const float4*)b1)[cg];
    const float4 b24 = ((const float4*)b2)[cg];

    // ---- GEMV 1 ----
    Acc4 z[8];
#pragma unroll
    for (int r = 0; r < 8; r++) z[r] = acc_init(b14);
#pragma unroll
    for (int k4 = 0; k4 < HID / 4; k4++) {
        ulonglong2 w0 = ((const ulonglong2*)w1sh)[(k4 * 4 + 0) * 16 + cg];
        ulonglong2 w1 = ((const ulonglong2*)w1sh)[(k4 * 4 + 1) * 16 + cg];
        ulonglong2 w2 = ((const ulonglong2*)w1sh)[(k4 * 4 + 2) * 16 + cg];
        ulonglong2 w3 = ((const ulonglong2*)w1sh)[(k4 * 4 + 3) * 16 + cg];
#pragma unroll
        for (int half = 0; half < 2; half++) {
            float4 s0 = ((const float4*)(trow + (half * 4 + 0) * HID))[k4];
            float4 s1 = ((const float4*)(trow + (half * 4 + 1) * HID))[k4];
            float4 s2 = ((const float4*)(trow + (half * 4 + 2) * HID))[k4];
            float4 s3 = ((const float4*)(trow + (half * 4 + 3) * HID))[k4];
            fma2x2(z[half*4+0], pack2s(s0.x), w0); fma2x2(z[half*4+0], pack2s(s0.y), w1);
            fma2x2(z[half*4+0], pack2s(s0.z), w2); fma2x2(z[half*4+0], pack2s(s0.w), w3);
            fma2x2(z[half*4+1], pack2s(s1.x), w0); fma2x2(z[half*4+1], pack2s(s1.y), w1);
            fma2x2(z[half*4+1], pack2s(s1.z), w2); fma2x2(z[half*4+1], pack2s(s1.w), w3);
            fma2x2(z[half*4+2], pack2s(s2.x), w0); fma2x2(z[half*4+2], pack2s(s2.y), w1);
            fma2x2(z[half*4+2], pack2s(s2.z), w2); fma2x2(z[half*4+2], pack2s(s2.w), w3);
            fma2x2(z[half*4+3], pack2s(s3.x), w0); fma2x2(z[half*4+3], pack2s(s3.y), w1);
            fma2x2(z[half*4+3], pack2s(s3.z), w2); fma2x2(z[half*4+3], pack2s(s3.w), w3);
        }
    }
    __syncwarp();   // warp done reading its tsh rows
#pragma unroll
    for (int r = 0; r < 8; r++)
        ((float4*)tsh)[(slot * 8 + r) * 16 + cg] = relu4(acc_to_f4(z[r]));
    __syncwarp();   // z visible within warp

    // ---- GEMV 2 ----
    Acc4 o[8];
#pragma unroll
    for (int r = 0; r < 8; r++) o[r] = acc_init(b24);
#pragma unroll
    for (int k4 = 0; k4 < HID / 4; k4++) {
        ulonglong2 w0 = ((const ulonglong2*)w2sh)[(k4 * 4 + 0) * 16 + cg];
        ulonglong2 w1 = ((const ulonglong2*)w2sh)[(k4 * 4 + 1) * 16 + cg];
        ulonglong2 w2 = ((const ulonglong2*)w2sh)[(k4 * 4 + 2) * 16 + cg];
        ulonglong2 w3 = ((const ulonglong2*)w2sh)[(k4 * 4 + 3) * 16 + cg];
#pragma unroll
        for (int half = 0; half < 2; half++) {
            float4 s0 = ((const float4*)(trow + (half * 4 + 0) * HID))[k4];
            float4 s1 = ((const float4*)(trow + (half * 4 + 1) * HID))[k4];
            float4 s2 = ((const float4*)(trow + (half * 4 + 2) * HID))[k4];
            float4 s3 = ((const float4*)(trow + (half * 4 + 3) * HID))[k4];
            fma2x2(o[half*4+0], pack2s(s0.x), w0); fma2x2(o[half*4+0], pack2s(s0.y), w1);
            fma2x2(o[half*4+0], pack2s(s0.z), w2); fma2x2(o[half*4+0], pack2s(s0.w), w3);
            fma2x2(o[half*4+1], pack2s(s1.x), w0); fma2x2(o[half*4+1], pack2s(s1.y), w1);
            fma2x2(o[half*4+1], pack2s(s1.z), w2); fma2x2(o[half*4+1], pack2s(s1.w), w3);
            fma2x2(o[half*4+2], pack2s(s2.x), w0); fma2x2(o[half*4+2], pack2s(s2.y), w1);
            fma2x2(o[half*4+2], pack2s(s2.z), w2); fma2x2(o[half*4+2], pack2s(s2.w), w3);
            fma2x2(o[half*4+3], pack2s(s3.x), w0); fma2x2(o[half*4+3], pack2s(s3.y), w1);
            fma2x2(o[half*4+3], pack2s(s3.z), w2); fma2x2(o[half*4+3], pack2s(s3.w), w3);
        }
    }
    int node0 = base + slot * 8;
#pragma unroll
    for (int r = 0; r < 8; r++) {
        int n = node0 + r;
        if (n < N_NODES) {
            float4 res = relu4(acc_to_f4(o[r]));
            ((float4*)(hout + (size_t)n * HID))[cg] = res;
            if (aggout)
                ((float4*)(aggout + (size_t)n * HID))[cg] = res;
        }
    }
}

// ---------------------------------------------------------------------------
// proj_out + pool v2: 64 nodes/block, 8 rows x 4 cols per thread.
// cg = lane (32 col-groups), slot = warp; warp stages its own 8 rows.
// Smem: w 32KB + h 16KB = 48KB -> 3 blocks/SM.
// ---------------------------------------------------------------------------
__global__ void __launch_bounds__(256, 3)
proj_out_pool_kernel(const float* __restrict__ h,
                     const int* __restrict__ batch,
                     const float* __restrict__ W,
                     const float* __restrict__ b,
                     float* __restrict__ pool) {
    __shared__ float wsh[HID * OUT_DIM];  // 32KB
    __shared__ float hsh[64 * HID];       // 16KB
    const int tid  = threadIdx.x;
    const int lane = tid & 31;
    const int warp = tid >> 5;
    const int base = blockIdx.x * 64;

    // (a) warp-local staging: rows 8w..8w+7 (each row 16 float4; 4/lane)
    {
        float4* d = (float4*)(hsh + (8 * warp) * HID);
        int rb = base + 8 * warp;
        if (rb + 8 <= N_NODES) {
            const float4* s = (const float4*)(h + (size_t)rb * HID);
#pragma unroll
            for (int it = 0; it < 4; it++)
                d[lane + 32 * it] = s[lane + 32 * it];
        } else {
#pragma unroll
            for (int it = 0; it < 4; it++) {
                int idx = lane + 32 * it;
                int row = idx >> 4, comp = idx & 15;
                int node = rb + row;
                if (node >= N_NODES) node = N_NODES - 1;
                d[row * 16 + comp] = ((const float4*)h)[(size_t)node * 16 + comp];
            }
        }
    }
    // (b) weights
    for (int i = tid; i < HID * OUT_DIM / 4; i += 256)
        ((float4*)wsh)[i] = ((const float4*)W)[i];
    __syncthreads();

    const int cg = lane;
    const float* trow = hsh + (size_t)warp * 8 * HID;
    const float4 b4 = ((const float4*)b)[cg];

    Acc4 a[8];
#pragma unroll
    for (int r = 0; r < 8; r++) a[r] = acc_init(b4);
#pragma unroll
    for (int k4 = 0; k4 < HID / 4; k4++) {
        ulonglong2 w0 = ((const ulonglong2*)wsh)[(k4 * 4 + 0) * 32 + cg];
        ulonglong2 w1 = ((const ulonglong2*)wsh)[(k4 * 4 + 1) * 32 + cg];
        ulonglong2 w2 = ((const ulonglong2*)wsh)[(k4 * 4 + 2) * 32 + cg];
        ulonglong2 w3 = ((const ulonglong2*)wsh)[(k4 * 4 + 3) * 32 + cg];
#pragma unroll
        for (int half = 0; half < 2; half++) {
            float4 s0 = ((const float4*)(trow + (half * 4 + 0) * HID))[k4];
            float4 s1 = ((const float4*)(trow + (half * 4 + 1) * HID))[k4];
            float4 s2 = ((const float4*)(trow + (half * 4 + 2) * HID))[k4];
            float4 s3 = ((const float4*)(trow + (half * 4 + 3) * HID))[k4];
            fma2x2(a[half*4+0], pack2s(s0.x), w0); fma2x2(a[half*4+0], pack2s(s0.y), w1);
            fma2x2(a[half*4+0], pack2s(s0.z), w2); fma2x2(a[half*4+0], pack2s(s0.w), w3);
            fma2x2(a[half*4+1], pack2s(s1.x), w0); fma2x2(a[half*4+1], pack2s(s1.y), w1);
            fma2x2(a[half*4+1], pack2s(s1.z), w2); fma2x2(a[half*4+1], pack2s(s1.w), w3);
            fma2x2(a[half*4+2], pack2s(s2.x), w0); fma2x2(a[half*4+2], pack2s(s2.y), w1);
            fma2x2(a[half*4+2], pack2s(s2.z), w2); fma2x2(a[half*4+2], pack2s(s2.w), w3);
            fma2x2(a[half*4+3], pack2s(s3.x), w0); fma2x2(a[half*4+3], pack2s(s3.y), w1);
            fma2x2(a[half*4+3], pack2s(s3.z), w2); fma2x2(a[half*4+3], pack2s(s3.w), w3);
        }
    }

    int node0 = base + warp * 8;
#pragma unroll
    for (int r = 0; r < 8; r++) {
        int n = node0 + r;
        if (n < N_NODES) {
            float4 v = acc_to_f4(a[r]);
            int g = __ldg(batch + n);
            float* addr = pool + g * OUT_DIM + cg * 4;
            asm volatile("red.global.add.v4.f32 [%0], {%1, %2, %3, %4};"
                         :: "l"(addr), "f"(v.x), "f"(v.y), "f"(v.z), "f"(v.w)
                         : "memory");
        }
    }
}

// ---------------------------------------------------------------------------
// finalize: counts via binary search on sorted batch (no atomics).
// ---------------------------------------------------------------------------
__global__ void finalize_kernel(const float* __restrict__ pool,
                                const int* __restrict__ batch,
                                float* __restrict__ out) {
    int i = blockIdx.x * blockDim.x + threadIdx.x;
    if (i >= N_GRAPHS * OUT_DIM) return;
    int g = i >> 7;
    int lo = 0, hi = N_NODES;
    while (lo < hi) { int m = (lo + hi) >> 1; if (__ldg(batch + m) <  g) lo = m + 1; else hi = m; }
    int start = lo;
    lo = 0; hi = N_NODES;
    while (lo < hi) { int m = (lo + hi) >> 1; if (__ldg(batch + m) <= g) lo = m + 1; else hi = m; }
    float c = (float)(lo - start);
    out[i] = pool[i] / fmaxf(c, 1.0f);
}

// ---------------------------------------------------------------------------
extern "C" void kernel_launch(void* const* d_in, const int* in_sizes, int n_in,
                              void* d_out, int out_size) {
    const float* x     = (const float*)d_in[0];
    const int*   ei    = (const int*)d_in[1];   // [2, E] int32
    const int*   batch = (const int*)d_in[2];   // [N] int32
    const float* W_in  = (const float*)d_in[3];
    const float* b_in  = (const float*)d_in[4];
    const float* W1_0  = (const float*)d_in[5];
    const float* b1_0  = (const float*)d_in[6];
    const float* W2_0  = (const float*)d_in[7];
    const float* b2_0  = (const float*)d_in[8];
    const float* W1_1  = (const float*)d_in[9];
    const float* b1_1  = (const float*)d_in[10];
    const float* W2_1  = (const float*)d_in[11];
    const float* b2_1  = (const float*)d_in[12];
    const float* W_out = (const float*)d_in[13];
    const float* b_out = (const float*)d_in[14];
    const int n_edges  = in_sizes[1] / 2;
    float* out = (float*)d_out;

    void* basep = nullptr;
    cudaGetSymbolAddress(&basep, g_scratch);
    float* h0   = (float*)basep;
    float* h1   = h0 + NH;
    float* a0   = h1 + NH;
    float* a1   = a0 + NH;
    float* pool = a1 + NH;

    // zero pool only (agg buffers are producer-initialized)
    zero_small_kernel<<<16, 256>>>(pool, N_GRAPHS * OUT_DIM / 4);

    cudaFuncSetAttribute(proj_in_kernel,
                         cudaFuncAttributeMaxDynamicSharedMemorySize, 57344);
    const int g48  = (N_NODES + 47) / 48;
    const int g128 = (N_NODES + 127) / 128;
    const int g64  = (N_NODES + 63) / 64;
    const int ge   = (n_edges * 16 + 255) / 256;

    proj_in_kernel<<<g48, 256, 57344>>>(x, W_in, b_in, h0, a0);
    scatter_kernel<<<ge, 256>>>(ei, h0, a0, n_edges);
    gin_mlp_kernel<<<g128, 256>>>(a0, W1_0, b1_0, W2_0, b2_0, h1, a1);
    scatter_kernel<<<ge, 256>>>(ei, h1, a1, n_edges);
    gin_mlp_kernel<<<g128, 256>>>(a1, W1_1, b1_1, W2_1, b2_1, h0, nullptr);
    proj_out_pool_kernel<<<g64, 256>>>(h0, batch, W_out, b_out, pool);
    finalize_kernel<<<(N_GRAPHS * OUT_DIM + 255) / 256, 256>>>(pool, batch, out);
}